// round 1
// baseline (speedup 1.0000x reference)
#include <cuda_runtime.h>

#define B_  4
#define LQ_ 2048
#define LK_ 2048
#define D_  1024

// Scratch: static device globals (no runtime allocation allowed).
__device__ float g_q[(size_t)B_ * LQ_ * D_];   // projected Q
__device__ float g_k[(size_t)B_ * LK_ * D_];   // projected K
__device__ float g_v[(size_t)B_ * LK_ * D_];   // projected V
__device__ float g_s[(size_t)B_ * LQ_ * LK_];  // attention scores / probs

// Generic fp32 SGEMM: C[M,N] = alpha * A[M,K] @ op(B) (+ bias)
//   TRANS_B=false: B stored [K,N] row-major (NN)
//   TRANS_B=true : B stored [N,K] row-major (NT)  -> used for Q @ K^T
// Batched via blockIdx.z with element strides sA/sB/sC.
// Tile: 128x128x8, 256 threads, 8x8 microtile per thread.
// All problem dims here are multiples of 128 (M) / 128 (N) / 8 (K): no bounds checks.
template <bool TRANS_B, bool BIAS>
__global__ __launch_bounds__(256)
void sgemm_k(const float* __restrict__ A, const float* __restrict__ Bm,
             const float* __restrict__ bias, float* __restrict__ C,
             int M, int N, int K, float alpha,
             size_t sA, size_t sB, size_t sC)
{
    __shared__ float As[8][128];
    __shared__ float Bs[8][128];

    const int tid = threadIdx.x;
    const int tx  = tid & 15;   // 0..15 -> 8 cols each
    const int ty  = tid >> 4;   // 0..15 -> 8 rows each
    const int m0  = blockIdx.y * 128;
    const int n0  = blockIdx.x * 128;

    const float* Ab = A  + (size_t)blockIdx.z * sA;
    const float* Bb = Bm + (size_t)blockIdx.z * sB;
    float*       Cb = C  + (size_t)blockIdx.z * sC;

    const int lr = tid >> 1;         // 0..127 (row of 128-row tile)
    const int lc = (tid & 1) * 4;    // 0 or 4 (k offset, float4)

    float acc[8][8];
#pragma unroll
    for (int i = 0; i < 8; i++)
#pragma unroll
        for (int j = 0; j < 8; j++) acc[i][j] = 0.f;

    for (int k0 = 0; k0 < K; k0 += 8) {
        // A tile: 128 x 8, stored transposed As[k][m]
        float4 av = *(const float4*)(Ab + (size_t)(m0 + lr) * K + (k0 + lc));
        As[lc + 0][lr] = av.x;
        As[lc + 1][lr] = av.y;
        As[lc + 2][lr] = av.z;
        As[lc + 3][lr] = av.w;

        if (TRANS_B) {
            // B stored [N,K]: need Bs[k][n] = B[n,k] -> scatter like A
            float4 bv = *(const float4*)(Bb + (size_t)(n0 + lr) * K + (k0 + lc));
            Bs[lc + 0][lr] = bv.x;
            Bs[lc + 1][lr] = bv.y;
            Bs[lc + 2][lr] = bv.z;
            Bs[lc + 3][lr] = bv.w;
        } else {
            // B stored [K,N]: direct coalesced float4
            const int bk = tid >> 5;        // 0..7
            const int bn = (tid & 31) * 4;  // 0..124
            *(float4*)&Bs[bk][bn] =
                *(const float4*)(Bb + (size_t)(k0 + bk) * N + (n0 + bn));
        }
        __syncthreads();

#pragma unroll
        for (int kk = 0; kk < 8; kk++) {
            float a[8], b[8];
            *(float4*)(a)     = *(const float4*)&As[kk][ty * 8];
            *(float4*)(a + 4) = *(const float4*)&As[kk][ty * 8 + 4];
            *(float4*)(b)     = *(const float4*)&Bs[kk][tx * 8];
            *(float4*)(b + 4) = *(const float4*)&Bs[kk][tx * 8 + 4];
#pragma unroll
            for (int i = 0; i < 8; i++)
#pragma unroll
                for (int j = 0; j < 8; j++)
                    acc[i][j] = fmaf(a[i], b[j], acc[i][j]);
        }
        __syncthreads();
    }

#pragma unroll
    for (int i = 0; i < 8; i++) {
        const int m = m0 + ty * 8 + i;
#pragma unroll
        for (int j = 0; j < 8; j += 4) {
            const int n = n0 + tx * 8 + j;
            float4 r;
            r.x = acc[i][j + 0] * alpha;
            r.y = acc[i][j + 1] * alpha;
            r.z = acc[i][j + 2] * alpha;
            r.w = acc[i][j + 3] * alpha;
            if (BIAS) {
                r.x += bias[n + 0];
                r.y += bias[n + 1];
                r.z += bias[n + 2];
                r.w += bias[n + 3];
            }
            *(float4*)(Cb + (size_t)m * N + n) = r;
        }
    }
}

// Row softmax over LK_=2048 columns. One block (256 threads) per row; 8 elems/thread.
__global__ __launch_bounds__(256)
void softmax_k(float* __restrict__ S)
{
    __shared__ float red[256];
    float* p = S + (size_t)blockIdx.x * LK_;
    const int tid = threadIdx.x;

    float v[8];
    *(float4*)(v)     = *(const float4*)(p + tid * 8);
    *(float4*)(v + 4) = *(const float4*)(p + tid * 8 + 4);

    float mx = v[0];
#pragma unroll
    for (int i = 1; i < 8; i++) mx = fmaxf(mx, v[i]);
    red[tid] = mx;
    __syncthreads();
    for (int s = 128; s > 0; s >>= 1) {
        if (tid < s) red[tid] = fmaxf(red[tid], red[tid + s]);
        __syncthreads();
    }
    mx = red[0];
    __syncthreads();

    float sum = 0.f;
#pragma unroll
    for (int i = 0; i < 8; i++) { v[i] = expf(v[i] - mx); sum += v[i]; }
    red[tid] = sum;
    __syncthreads();
    for (int s = 128; s > 0; s >>= 1) {
        if (tid < s) red[tid] += red[tid + s];
        __syncthreads();
    }
    const float inv = 1.f / red[0];
    __syncthreads();

#pragma unroll
    for (int i = 0; i < 8; i++) v[i] *= inv;
    *(float4*)(p + tid * 8)     = *(float4*)(v);
    *(float4*)(p + tid * 8 + 4) = *(float4*)(v + 4);
}

extern "C" void kernel_launch(void* const* d_in, const int* in_sizes, int n_in,
                              void* d_out, int out_size)
{
    const float* q_in = (const float*)d_in[0];
    const float* k_in = (const float*)d_in[1];
    const float* v_in = (const float*)d_in[2];
    const float* Wq   = (const float*)d_in[3];
    const float* bq   = (const float*)d_in[4];
    const float* Wk   = (const float*)d_in[5];
    const float* bk   = (const float*)d_in[6];
    const float* Wv   = (const float*)d_in[7];
    const float* bv   = (const float*)d_in[8];
    float* out = (float*)d_out;

    float *pq, *pk, *pv, *ps;
    cudaGetSymbolAddress((void**)&pq, g_q);
    cudaGetSymbolAddress((void**)&pk, g_k);
    cudaGetSymbolAddress((void**)&pv, g_v);
    cudaGetSymbolAddress((void**)&ps, g_s);

    dim3 blk(256);

    // Projections: [8192,1024] = [8192,1024] @ [1024,1024] + bias
    dim3 gp(D_ / 128, (B_ * LQ_) / 128, 1);
    sgemm_k<false, true><<<gp, blk>>>(q_in, Wq, bq, pq, B_ * LQ_, D_, D_, 1.f, 0, 0, 0);
    sgemm_k<false, true><<<gp, blk>>>(k_in, Wk, bk, pk, B_ * LK_, D_, D_, 1.f, 0, 0, 0);
    sgemm_k<false, true><<<gp, blk>>>(v_in, Wv, bv, pv, B_ * LK_, D_, D_, 1.f, 0, 0, 0);

    // Scores: S[b] = (Q[b] @ K[b]^T) / sqrt(1024)
    dim3 gs(LK_ / 128, LQ_ / 128, B_);
    sgemm_k<true, false><<<gs, blk>>>(pq, pk, nullptr, ps, LQ_, LK_, D_, 1.f / 32.f,
                                      (size_t)LQ_ * D_, (size_t)LK_ * D_,
                                      (size_t)LQ_ * LK_);

    // Softmax rows
    softmax_k<<<B_ * LQ_, 256>>>(ps);

    // Output: O[b] = P[b] @ V[b]
    dim3 go(D_ / 128, LQ_ / 128, B_);
    sgemm_k<false, false><<<go, blk>>>(ps, pv, nullptr, out, LQ_, D_, LK_, 1.f,
                                       (size_t)LQ_ * LK_, (size_t)LK_ * D_,
                                       (size_t)LQ_ * D_);
}

// round 3
// speedup vs baseline: 5.8502x; 5.8502x over previous
#include <cuda_runtime.h>
#include <cstdint>

#define B_  4
#define LQ_ 2048
#define LK_ 2048
#define D_  1024

// ---------------- scratch (static device globals; no runtime alloc) ----------
__device__ float g_x   [(size_t)3 * B_ * LQ_ * D_];  // rounded inputs, stacked q|k|v
__device__ float g_wt  [(size_t)3 * D_ * D_];        // W^T rounded, stacked
__device__ float g_bias[3 * D_];                     // biases stacked
__device__ float g_qkv [(size_t)3 * B_ * LQ_ * D_];  // projected q|k|v (tf32-rounded)
__device__ float g_vt  [(size_t)B_ * D_ * LK_];      // V^T per batch (tf32-rounded)
__device__ float g_s   [(size_t)B_ * LQ_ * LK_];     // scores / probs

// ---------------- PTX helpers ------------------------------------------------
__device__ __forceinline__ uint32_t smem_u32(const void* p) {
    uint32_t a;
    asm("{ .reg .u64 t; cvta.to.shared.u64 t, %1; cvt.u32.u64 %0, t; }" : "=r"(a) : "l"(p));
    return a;
}
__device__ __forceinline__ float rna_tf32(float x) {
    uint32_t r; asm("cvt.rna.tf32.f32 %0, %1;" : "=r"(r) : "f"(x));
    return __uint_as_float(r);
}
__device__ __forceinline__ void cp16(uint32_t s, const void* g) {
    asm volatile("cp.async.cg.shared.global [%0], [%1], 16;" :: "r"(s), "l"(g));
}
#define CP_COMMIT() asm volatile("cp.async.commit_group;" ::: "memory")
#define CP_WAIT(n)  asm volatile("cp.async.wait_group %0;" :: "n"(n) : "memory")

__device__ __forceinline__ void mma_tf32(float* c, const uint32_t* a, const uint32_t* b) {
    asm volatile(
        "mma.sync.aligned.m16n8k8.row.col.f32.tf32.tf32.f32 "
        "{%0,%1,%2,%3}, {%4,%5,%6,%7}, {%8,%9}, {%0,%1,%2,%3};"
        : "+f"(c[0]), "+f"(c[1]), "+f"(c[2]), "+f"(c[3])
        : "r"(a[0]), "r"(a[1]), "r"(a[2]), "r"(a[3]), "r"(b[0]), "r"(b[1]));
}

// ---------------- tf32 mma.sync NT GEMM --------------------------------------
// C[M,N] = alpha * A[M,K] @ Bt[N,K]^T (+ bias), batched via blockIdx.z.
// Operand buffers must already hold tf32-rounded values.
// Tile 128x128x16, 256 threads (2x4 warp grid, 64x32 warp tiles), 3-stage cp.async.
#define BM 128
#define BN 128
#define BK 16
#define RST 20                         // smem row stride (floats): conflict-free
#define STAGE_FLOATS ((BM + BN) * RST) // 5120 floats = 20KB
#define STAGES 3
#define GEMM_SMEM (STAGES * STAGE_FLOATS * 4)

template <bool BIAS, bool ROUND>
__global__ __launch_bounds__(256, 2)
void gemm_tf32(const float* __restrict__ A, const float* __restrict__ Bt,
               const float* __restrict__ bias, float* __restrict__ C,
               int M, int N, int K, float alpha,
               size_t sA, size_t sB, size_t sC, int sBias)
{
    extern __shared__ float smf[];
    const uint32_t sb32 = smem_u32(smf);

    const int tid  = threadIdx.x;
    const int wid  = tid >> 5;
    const int lane = tid & 31;
    const int grp  = lane >> 2;   // 0..7
    const int q    = lane & 3;    // 0..3
    const int wm   = wid & 1;     // 2 warps along M -> 64 rows each
    const int wn   = wid >> 1;    // 4 warps along N -> 32 cols each

    const int m0 = blockIdx.y * BM;
    const int n0 = blockIdx.x * BN;

    const float* Ab = A  + (size_t)blockIdx.z * sA;
    const float* Bb = Bt + (size_t)blockIdx.z * sB;
    const float* biasb = BIAS ? (bias + (size_t)blockIdx.z * sBias) : nullptr;
    float* Cb = C + (size_t)blockIdx.z * sC;

    const int KT = K / BK;

    // async load of one stage (A tile 128x16 + B tile 128x16, both K-major)
    auto load_stage = [&](int s, int kt) {
        const uint32_t abase = sb32 + s * STAGE_FLOATS * 4;
        const uint32_t bbase = abase + BM * RST * 4;
        const int k0 = kt * BK;
#pragma unroll
        for (int j = 0; j < 2; j++) {
            const int idx = tid + j * 256;      // 0..511
            const int row = idx >> 2;           // 0..127
            const int seg = idx & 3;            // 16B segment within 64B row
            cp16(abase + (row * RST + seg * 4) * 4,
                 Ab + (size_t)(m0 + row) * K + k0 + seg * 4);
            cp16(bbase + (row * RST + seg * 4) * 4,
                 Bb + (size_t)(n0 + row) * K + k0 + seg * 4);
        }
        CP_COMMIT();
    };

    float acc[4][4][4];
#pragma unroll
    for (int i = 0; i < 4; i++)
#pragma unroll
        for (int j = 0; j < 4; j++)
#pragma unroll
            for (int r = 0; r < 4; r++) acc[i][j][r] = 0.f;

    load_stage(0, 0);
    if (KT > 1) load_stage(1, 1);
    if (KT > 2) load_stage(2, 2);

    for (int kt = 0; kt < KT; kt++) {
        const int s = kt % STAGES;
        const int rem = KT - 1 - kt;
        if (rem >= 2) { CP_WAIT(2); } else if (rem == 1) { CP_WAIT(1); } else { CP_WAIT(0); }
        __syncthreads();

        const float* sa = smf + s * STAGE_FLOATS;
        const float* sbm = sa + BM * RST;

#pragma unroll
        for (int kk = 0; kk < 2; kk++) {
            uint32_t af[4][4], bf[4][2];
            const int kb = kk * 8 + q;
#pragma unroll
            for (int mt = 0; mt < 4; mt++) {
                const int r = wm * 64 + mt * 16 + grp;
                af[mt][0] = __float_as_uint(sa[r * RST + kb]);
                af[mt][1] = __float_as_uint(sa[(r + 8) * RST + kb]);
                af[mt][2] = __float_as_uint(sa[r * RST + kb + 4]);
                af[mt][3] = __float_as_uint(sa[(r + 8) * RST + kb + 4]);
            }
#pragma unroll
            for (int nt = 0; nt < 4; nt++) {
                const int c = wn * 32 + nt * 8 + grp;
                bf[nt][0] = __float_as_uint(sbm[c * RST + kb]);
                bf[nt][1] = __float_as_uint(sbm[c * RST + kb + 4]);
            }
#pragma unroll
            for (int mt = 0; mt < 4; mt++)
#pragma unroll
                for (int nt = 0; nt < 4; nt++)
                    mma_tf32(acc[mt][nt], af[mt], bf[nt]);
        }
        __syncthreads();

        if (kt + STAGES < KT) load_stage((kt + STAGES) % STAGES, kt + STAGES);
    }

    // Epilogue: c0,c1 -> (row, 2q..2q+1), c2,c3 -> (row+8, ...)
#pragma unroll
    for (int mt = 0; mt < 4; mt++) {
        const int r = m0 + wm * 64 + mt * 16 + grp;
#pragma unroll
        for (int nt = 0; nt < 4; nt++) {
            const int c = n0 + wn * 32 + nt * 8 + q * 2;
            float2 v0, v1;
            v0.x = acc[mt][nt][0] * alpha;
            v0.y = acc[mt][nt][1] * alpha;
            v1.x = acc[mt][nt][2] * alpha;
            v1.y = acc[mt][nt][3] * alpha;
            if (BIAS) {
                const float2 bb = *(const float2*)(biasb + c);
                v0.x += bb.x; v0.y += bb.y;
                v1.x += bb.x; v1.y += bb.y;
            }
            if (ROUND) {
                v0.x = rna_tf32(v0.x); v0.y = rna_tf32(v0.y);
                v1.x = rna_tf32(v1.x); v1.y = rna_tf32(v1.y);
            }
            *(float2*)(Cb + (size_t)r * N + c)       = v0;
            *(float2*)(Cb + (size_t)(r + 8) * N + c) = v1;
        }
    }
}

// ---------------- aux kernels ------------------------------------------------
__global__ __launch_bounds__(256)
void round_copy_k(const float* __restrict__ in, float* __restrict__ out, int n4)
{
    const int i = blockIdx.x * 256 + threadIdx.x;
    if (i < n4) {
        float4 v = ((const float4*)in)[i];
        v.x = rna_tf32(v.x); v.y = rna_tf32(v.y);
        v.z = rna_tf32(v.z); v.w = rna_tf32(v.w);
        ((float4*)out)[i] = v;
    }
}

// in [R,C] row-major -> out [C,R] row-major, tf32-rounded, batched.
__global__ __launch_bounds__(256)
void transpose_round_k(const float* __restrict__ in, float* __restrict__ out,
                       int R, int C, size_t sIn, size_t sOut)
{
    __shared__ float t[32][33];
    const float* ib = in  + (size_t)blockIdx.z * sIn;
    float*       ob = out + (size_t)blockIdx.z * sOut;
    const int c0 = blockIdx.x * 32, r0 = blockIdx.y * 32;
    const int tx = threadIdx.x & 31, ty = threadIdx.x >> 5;  // 32x8
#pragma unroll
    for (int i = 0; i < 32; i += 8)
        t[ty + i][tx] = ib[(size_t)(r0 + ty + i) * C + c0 + tx];
    __syncthreads();
#pragma unroll
    for (int i = 0; i < 32; i += 8)
        ob[(size_t)(c0 + ty + i) * R + r0 + tx] = rna_tf32(t[tx][ty + i]);
}

// Row softmax over LK_ columns; tf32-rounded output.
__global__ __launch_bounds__(256)
void softmax_k(float* __restrict__ S)
{
    __shared__ float red[256];
    float* p = S + (size_t)blockIdx.x * LK_;
    const int tid = threadIdx.x;

    float v[8];
    *(float4*)(v)     = *(const float4*)(p + tid * 8);
    *(float4*)(v + 4) = *(const float4*)(p + tid * 8 + 4);

    float mx = v[0];
#pragma unroll
    for (int i = 1; i < 8; i++) mx = fmaxf(mx, v[i]);
    red[tid] = mx;
    __syncthreads();
    for (int s = 128; s > 0; s >>= 1) {
        if (tid < s) red[tid] = fmaxf(red[tid], red[tid + s]);
        __syncthreads();
    }
    mx = red[0];
    __syncthreads();

    float sum = 0.f;
#pragma unroll
    for (int i = 0; i < 8; i++) { v[i] = __expf(v[i] - mx); sum += v[i]; }
    red[tid] = sum;
    __syncthreads();
    for (int s = 128; s > 0; s >>= 1) {
        if (tid < s) red[tid] += red[tid + s];
        __syncthreads();
    }
    const float inv = 1.f / red[0];
    __syncthreads();

#pragma unroll
    for (int i = 0; i < 8; i++) v[i] = rna_tf32(v[i] * inv);
    *(float4*)(p + tid * 8)     = *(float4*)(v);
    *(float4*)(p + tid * 8 + 4) = *(float4*)(v + 4);
}

// ---------------- host -------------------------------------------------------
extern "C" void kernel_launch(void* const* d_in, const int* in_sizes, int n_in,
                              void* d_out, int out_size)
{
    const float* q_in = (const float*)d_in[0];
    const float* k_in = (const float*)d_in[1];
    const float* v_in = (const float*)d_in[2];
    const float* Wq   = (const float*)d_in[3];
    const float* bq   = (const float*)d_in[4];
    const float* Wk   = (const float*)d_in[5];
    const float* bk   = (const float*)d_in[6];
    const float* Wv   = (const float*)d_in[7];
    const float* bv   = (const float*)d_in[8];
    float* out = (float*)d_out;

    float *px, *pwt, *pbias, *pqkv, *pvt, *ps;
    cudaGetSymbolAddress((void**)&px,    g_x);
    cudaGetSymbolAddress((void**)&pwt,   g_wt);
    cudaGetSymbolAddress((void**)&pbias, g_bias);
    cudaGetSymbolAddress((void**)&pqkv,  g_qkv);
    cudaGetSymbolAddress((void**)&pvt,   g_vt);
    cudaGetSymbolAddress((void**)&ps,    g_s);

    cudaFuncSetAttribute((const void*)gemm_tf32<true,  true >,
                         cudaFuncAttributeMaxDynamicSharedMemorySize, GEMM_SMEM);
    cudaFuncSetAttribute((const void*)gemm_tf32<false, false>,
                         cudaFuncAttributeMaxDynamicSharedMemorySize, GEMM_SMEM);

    const size_t T = (size_t)B_ * LQ_ * D_;
    const int n4 = (int)(T / 4);

    // 1) round inputs to tf32, stacked
    round_copy_k<<<(n4 + 255) / 256, 256>>>(q_in, px + 0 * T, n4);
    round_copy_k<<<(n4 + 255) / 256, 256>>>(k_in, px + 1 * T, n4);
    round_copy_k<<<(n4 + 255) / 256, 256>>>(v_in, px + 2 * T, n4);

    // 2) W^T (rounded), biases stacked
    dim3 tb(256);
    transpose_round_k<<<dim3(D_ / 32, D_ / 32, 1), tb>>>(Wq, pwt + 0 * (size_t)D_ * D_, D_, D_, 0, 0);
    transpose_round_k<<<dim3(D_ / 32, D_ / 32, 1), tb>>>(Wk, pwt + 1 * (size_t)D_ * D_, D_, D_, 0, 0);
    transpose_round_k<<<dim3(D_ / 32, D_ / 32, 1), tb>>>(Wv, pwt + 2 * (size_t)D_ * D_, D_, D_, 0, 0);
    cudaMemcpyAsync(pbias + 0 * D_, bq, D_ * sizeof(float), cudaMemcpyDeviceToDevice);
    cudaMemcpyAsync(pbias + 1 * D_, bk, D_ * sizeof(float), cudaMemcpyDeviceToDevice);
    cudaMemcpyAsync(pbias + 2 * D_, bv, D_ * sizeof(float), cudaMemcpyDeviceToDevice);

    // 3) projections: one batched launch over q|k|v (bias + tf32-rounded output)
    gemm_tf32<true, true><<<dim3(D_ / BN, (B_ * LQ_) / BM, 3), 256, GEMM_SMEM>>>(
        px, pwt, pbias, pqkv, B_ * LQ_, D_, D_, 1.f,
        T, (size_t)D_ * D_, T, D_);

    // 4) V^T per batch (rounded)
    transpose_round_k<<<dim3(D_ / 32, LK_ / 32, B_), tb>>>(
        pqkv + 2 * T, pvt, LK_, D_, (size_t)LK_ * D_, (size_t)D_ * LK_);

    // 5) scores S = (Q K^T) / 32
    gemm_tf32<false, false><<<dim3(LK_ / BN, LQ_ / BM, B_), 256, GEMM_SMEM>>>(
        pqkv + 0 * T, pqkv + 1 * T, nullptr, ps, LQ_, LK_, D_, 1.f / 32.f,
        (size_t)LQ_ * D_, (size_t)LK_ * D_, (size_t)LQ_ * LK_, 0);

    // 6) softmax rows (tf32-rounded probs)
    softmax_k<<<B_ * LQ_, 256>>>(ps);

    // 7) O = P @ V  (V^T is [D, LK] K-major)
    gemm_tf32<false, false><<<dim3(D_ / BN, LQ_ / BM, B_), 256, GEMM_SMEM>>>(
        ps, pvt, nullptr, out, LQ_, D_, LK_, 1.f,
        (size_t)LQ_ * LK_, (size_t)D_ * LK_, (size_t)LQ_ * D_, 0);
}

// round 4
// speedup vs baseline: 6.2739x; 1.0724x over previous
#include <cuda_runtime.h>
#include <cstdint>

#define B_  4
#define LQ_ 2048
#define LK_ 2048
#define D_  1024

// ---------------- scratch (static device globals; no runtime alloc) ----------
__device__ float g_wt  [(size_t)3 * D_ * D_];        // W^T rounded, stacked
__device__ float g_bias[3 * D_];                     // biases stacked
__device__ float g_qkv [(size_t)3 * B_ * LQ_ * D_];  // projected q|k|v (tf32-rounded)
__device__ float g_vt  [(size_t)B_ * D_ * LK_];      // V^T per batch (tf32-rounded)
__device__ float g_s   [(size_t)B_ * LQ_ * LK_];     // scores / probs

// ---------------- PTX helpers ------------------------------------------------
__device__ __forceinline__ uint32_t smem_u32(const void* p) {
    uint32_t a;
    asm("{ .reg .u64 t; cvta.to.shared.u64 t, %1; cvt.u32.u64 %0, t; }" : "=r"(a) : "l"(p));
    return a;
}
__device__ __forceinline__ float rna_tf32(float x) {
    uint32_t r; asm("cvt.rna.tf32.f32 %0, %1;" : "=r"(r) : "f"(x));
    return __uint_as_float(r);
}
__device__ __forceinline__ uint32_t rna_tf32_u(uint32_t x) {
    uint32_t r; asm("cvt.rna.tf32.f32 %0, %1;" : "=r"(r) : "f"(__uint_as_float(x)));
    return r;
}
__device__ __forceinline__ void cp16(uint32_t s, const void* g) {
    asm volatile("cp.async.cg.shared.global [%0], [%1], 16;" :: "r"(s), "l"(g));
}
#define CP_COMMIT() asm volatile("cp.async.commit_group;" ::: "memory")
#define CP_WAIT(n)  asm volatile("cp.async.wait_group %0;" :: "n"(n) : "memory")

__device__ __forceinline__ void ldsm4(uint32_t* r, uint32_t addr) {
    asm volatile("ldmatrix.sync.aligned.m8n8.x4.shared.b16 {%0,%1,%2,%3}, [%4];"
        : "=r"(r[0]), "=r"(r[1]), "=r"(r[2]), "=r"(r[3]) : "r"(addr));
}

__device__ __forceinline__ void mma_tf32(float* c, const uint32_t* a, const uint32_t* b) {
    asm volatile(
        "mma.sync.aligned.m16n8k8.row.col.f32.tf32.tf32.f32 "
        "{%0,%1,%2,%3}, {%4,%5,%6,%7}, {%8,%9}, {%0,%1,%2,%3};"
        : "+f"(c[0]), "+f"(c[1]), "+f"(c[2]), "+f"(c[3])
        : "r"(a[0]), "r"(a[1]), "r"(a[2]), "r"(a[3]), "r"(b[0]), "r"(b[1]));
}

// ---------------- tf32 mma.sync NT GEMM --------------------------------------
// C[M,N] = alpha * A[M,K] @ Bt[N,K]^T (+ bias), batched via blockIdx.z.
// Block tile 128x256x32; 256 threads = 8 warps (2 M x 4 N), warp tile 64x64.
// A/B smem K-major, row stride RST=36 floats (bank-balanced for ldmatrix + cp.async).
#define BM 128
#define BN 256
#define BK 32
#define RST 36
#define STAGE_FLOATS ((BM + BN) * RST)   // 13824 floats = 55296 B
#define STAGES 3
#define GEMM_SMEM (STAGES * STAGE_FLOATS * 4)

template <bool MULTI_A, bool RND_A, bool BIAS, bool ROUND>
__global__ __launch_bounds__(256, 1)
void gemm_tf32(const float* __restrict__ A0, const float* __restrict__ A1,
               const float* __restrict__ A2, const float* __restrict__ Bt,
               const float* __restrict__ bias, float* __restrict__ C,
               int N, int K, float alpha,
               size_t sA, size_t sB, size_t sC, int sBias)
{
    extern __shared__ float smf[];
    const uint32_t sb32 = smem_u32(smf);

    const int tid  = threadIdx.x;
    const int wid  = tid >> 5;
    const int lane = tid & 31;
    const int grp  = lane >> 2;   // 0..7
    const int q    = lane & 3;    // 0..3
    const int wm   = wid & 1;     // 2 warps along M -> 64 rows
    const int wn   = wid >> 1;    // 4 warps along N -> 64 cols

    const int m0 = blockIdx.y * BM;
    const int n0 = blockIdx.x * BN;
    const int z  = blockIdx.z;

    const float* Ab = MULTI_A ? (z == 0 ? A0 : (z == 1 ? A1 : A2))
                              : A0 + (size_t)z * sA;
    const float* Bb = Bt + (size_t)z * sB;
    const float* biasb = BIAS ? (bias + (size_t)z * sBias) : nullptr;
    float* Cb = C + (size_t)z * sC;

    const int KT = K / BK;

    // per-lane ldmatrix byte offsets (within stage base / B region base)
    const uint32_t aoff =
        ((wm * 64 + (lane & 7) + ((lane >> 3) & 1) * 8) * RST + ((lane >> 4) & 1) * 4) * 4;
    const uint32_t boff =
        ((wn * 64 + (lane & 7) + ((lane >> 4) & 1) * 8) * RST + ((lane >> 3) & 1) * 4) * 4;

    // async load of one stage: A 128x32, B 256x32, K-major rows (8 x 16B segs)
    auto load_stage = [&](int s, int kt) {
        const uint32_t abase = sb32 + s * STAGE_FLOATS * 4;
        const uint32_t bbase = abase + BM * RST * 4;
        const int k0 = kt * BK;
#pragma unroll
        for (int j = 0; j < 4; j++) {
            const int idx = tid + j * 256;          // 0..1023
            const int row = idx >> 3, seg = idx & 7;
            cp16(abase + (row * RST + seg * 4) * 4,
                 Ab + (size_t)(m0 + row) * K + k0 + seg * 4);
        }
#pragma unroll
        for (int j = 0; j < 8; j++) {
            const int idx = tid + j * 256;          // 0..2047
            const int row = idx >> 3, seg = idx & 7;
            cp16(bbase + (row * RST + seg * 4) * 4,
                 Bb + (size_t)(n0 + row) * K + k0 + seg * 4);
        }
        CP_COMMIT();
    };

    float acc[4][8][4];
#pragma unroll
    for (int i = 0; i < 4; i++)
#pragma unroll
        for (int j = 0; j < 8; j++)
#pragma unroll
            for (int r = 0; r < 4; r++) acc[i][j][r] = 0.f;

    load_stage(0, 0);
    if (KT > 1) load_stage(1, 1);
    if (KT > 2) load_stage(2, 2);

    for (int kt = 0; kt < KT; kt++) {
        const int s = kt % STAGES;
        const int rem = KT - 1 - kt;
        if (rem >= 2) { CP_WAIT(2); } else if (rem == 1) { CP_WAIT(1); } else { CP_WAIT(0); }
        __syncthreads();

        const uint32_t sa = sb32 + s * STAGE_FLOATS * 4;
        const uint32_t sbB = sa + BM * RST * 4;

#pragma unroll
        for (int kk = 0; kk < 4; kk++) {
            uint32_t af[4][4], bf[4][4];
#pragma unroll
            for (int mt = 0; mt < 4; mt++)
                ldsm4(af[mt], sa + aoff + mt * (16 * RST * 4) + kk * 32);
            if (RND_A) {
#pragma unroll
                for (int mt = 0; mt < 4; mt++)
#pragma unroll
                    for (int r = 0; r < 4; r++) af[mt][r] = rna_tf32_u(af[mt][r]);
            }
#pragma unroll
            for (int ntp = 0; ntp < 4; ntp++)
                ldsm4(bf[ntp], sbB + boff + ntp * (16 * RST * 4) + kk * 32);
#pragma unroll
            for (int mt = 0; mt < 4; mt++)
#pragma unroll
                for (int nt = 0; nt < 8; nt++)
                    mma_tf32(acc[mt][nt], af[mt], bf[nt >> 1] + (nt & 1) * 2);
        }
        __syncthreads();

        if (kt + STAGES < KT) load_stage((kt + STAGES) % STAGES, kt + STAGES);
    }

    // Epilogue: acc[mt][nt] -> rows r, r+8 ; cols c..c+1
#pragma unroll
    for (int mt = 0; mt < 4; mt++) {
        const int r = m0 + wm * 64 + mt * 16 + grp;
#pragma unroll
        for (int nt = 0; nt < 8; nt++) {
            const int c = n0 + wn * 64 + nt * 8 + q * 2;
            float2 v0, v1;
            v0.x = acc[mt][nt][0] * alpha;
            v0.y = acc[mt][nt][1] * alpha;
            v1.x = acc[mt][nt][2] * alpha;
            v1.y = acc[mt][nt][3] * alpha;
            if (BIAS) {
                const float2 bb = *(const float2*)(biasb + c);
                v0.x += bb.x; v0.y += bb.y;
                v1.x += bb.x; v1.y += bb.y;
            }
            if (ROUND) {
                v0.x = rna_tf32(v0.x); v0.y = rna_tf32(v0.y);
                v1.x = rna_tf32(v1.x); v1.y = rna_tf32(v1.y);
            }
            *(float2*)(Cb + (size_t)r * N + c)       = v0;
            *(float2*)(Cb + (size_t)(r + 8) * N + c) = v1;
        }
    }
}

// ---------------- aux kernels ------------------------------------------------
// in [R,C] row-major -> out [C,R] row-major, tf32-rounded, batched.
__global__ __launch_bounds__(256)
void transpose_round_k(const float* __restrict__ in, float* __restrict__ out,
                       int R, int C, size_t sIn, size_t sOut)
{
    __shared__ float t[32][33];
    const float* ib = in  + (size_t)blockIdx.z * sIn;
    float*       ob = out + (size_t)blockIdx.z * sOut;
    const int c0 = blockIdx.x * 32, r0 = blockIdx.y * 32;
    const int tx = threadIdx.x & 31, ty = threadIdx.x >> 5;  // 32x8
#pragma unroll
    for (int i = 0; i < 32; i += 8)
        t[ty + i][tx] = ib[(size_t)(r0 + ty + i) * C + c0 + tx];
    __syncthreads();
#pragma unroll
    for (int i = 0; i < 32; i += 8)
        ob[(size_t)(c0 + ty + i) * R + r0 + tx] = rna_tf32(t[tx][ty + i]);
}

// Row softmax over LK_ columns; tf32-rounded output.
__global__ __launch_bounds__(256)
void softmax_k(float* __restrict__ S)
{
    __shared__ float red[256];
    float* p = S + (size_t)blockIdx.x * LK_;
    const int tid = threadIdx.x;

    float v[8];
    *(float4*)(v)     = *(const float4*)(p + tid * 8);
    *(float4*)(v + 4) = *(const float4*)(p + tid * 8 + 4);

    float mx = v[0];
#pragma unroll
    for (int i = 1; i < 8; i++) mx = fmaxf(mx, v[i]);
    red[tid] = mx;
    __syncthreads();
    for (int s = 128; s > 0; s >>= 1) {
        if (tid < s) red[tid] = fmaxf(red[tid], red[tid + s]);
        __syncthreads();
    }
    mx = red[0];
    __syncthreads();

    float sum = 0.f;
#pragma unroll
    for (int i = 0; i < 8; i++) { v[i] = __expf(v[i] - mx); sum += v[i]; }
    red[tid] = sum;
    __syncthreads();
    for (int s = 128; s > 0; s >>= 1) {
        if (tid < s) red[tid] += red[tid + s];
        __syncthreads();
    }
    const float inv = 1.f / red[0];
    __syncthreads();

#pragma unroll
    for (int i = 0; i < 8; i++) v[i] = rna_tf32(v[i] * inv);
    *(float4*)(p + tid * 8)     = *(float4*)(v);
    *(float4*)(p + tid * 8 + 4) = *(float4*)(v + 4);
}

// ---------------- host -------------------------------------------------------
extern "C" void kernel_launch(void* const* d_in, const int* in_sizes, int n_in,
                              void* d_out, int out_size)
{
    const float* q_in = (const float*)d_in[0];
    const float* k_in = (const float*)d_in[1];
    const float* v_in = (const float*)d_in[2];
    const float* Wq   = (const float*)d_in[3];
    const float* bq   = (const float*)d_in[4];
    const float* Wk   = (const float*)d_in[5];
    const float* bk   = (const float*)d_in[6];
    const float* Wv   = (const float*)d_in[7];
    const float* bv   = (const float*)d_in[8];
    float* out = (float*)d_out;

    float *pwt, *pbias, *pqkv, *pvt, *ps;
    cudaGetSymbolAddress((void**)&pwt,   g_wt);
    cudaGetSymbolAddress((void**)&pbias, g_bias);
    cudaGetSymbolAddress((void**)&pqkv,  g_qkv);
    cudaGetSymbolAddress((void**)&pvt,   g_vt);
    cudaGetSymbolAddress((void**)&ps,    g_s);

    cudaFuncSetAttribute((const void*)gemm_tf32<true,  true,  true,  true >,
                         cudaFuncAttributeMaxDynamicSharedMemorySize, GEMM_SMEM);
    cudaFuncSetAttribute((const void*)gemm_tf32<false, false, false, false>,
                         cudaFuncAttributeMaxDynamicSharedMemorySize, GEMM_SMEM);

    const size_t T = (size_t)B_ * LQ_ * D_;

    // 1) W^T (rounded), biases stacked
    dim3 tb(256);
    transpose_round_k<<<dim3(D_ / 32, D_ / 32, 1), tb>>>(Wq, pwt + 0 * (size_t)D_ * D_, D_, D_, 0, 0);
    transpose_round_k<<<dim3(D_ / 32, D_ / 32, 1), tb>>>(Wk, pwt + 1 * (size_t)D_ * D_, D_, D_, 0, 0);
    transpose_round_k<<<dim3(D_ / 32, D_ / 32, 1), tb>>>(Wv, pwt + 2 * (size_t)D_ * D_, D_, D_, 0, 0);
    cudaMemcpyAsync(pbias + 0 * D_, bq, D_ * sizeof(float), cudaMemcpyDeviceToDevice);
    cudaMemcpyAsync(pbias + 1 * D_, bk, D_ * sizeof(float), cudaMemcpyDeviceToDevice);
    cudaMemcpyAsync(pbias + 2 * D_, bv, D_ * sizeof(float), cudaMemcpyDeviceToDevice);

    // 2) projections: batched over z (q|k|v), A rounded in-register, out rounded
    gemm_tf32<true, true, true, true><<<dim3(D_ / BN, (B_ * LQ_) / BM, 3), 256, GEMM_SMEM>>>(
        q_in, k_in, v_in, pwt, pbias, pqkv, D_, D_, 1.f,
        0, (size_t)D_ * D_, T, D_);

    // 3) V^T per batch (rounded)
    transpose_round_k<<<dim3(D_ / 32, LK_ / 32, B_), tb>>>(
        pqkv + 2 * T, pvt, LK_, D_, (size_t)LK_ * D_, (size_t)D_ * LK_);

    // 4) scores S = (Q K^T) / 32
    gemm_tf32<false, false, false, false><<<dim3(LK_ / BN, LQ_ / BM, B_), 256, GEMM_SMEM>>>(
        pqkv + 0 * T, nullptr, nullptr, pqkv + 1 * T, nullptr, ps, LK_, D_, 1.f / 32.f,
        (size_t)LQ_ * D_, (size_t)LK_ * D_, (size_t)LQ_ * LK_, 0);

    // 5) softmax rows (tf32-rounded probs)
    softmax_k<<<B_ * LQ_, 256>>>(ps);

    // 6) O = P @ V  (V^T is [D, LK] K-major)
    gemm_tf32<false, false, false, false><<<dim3(D_ / BN, LQ_ / BM, B_), 256, GEMM_SMEM>>>(
        ps, nullptr, nullptr, pvt, nullptr, out, D_, LK_, 1.f,
        (size_t)LQ_ * LK_, (size_t)D_ * LK_, (size_t)LQ_ * D_, 0);
}

// round 5
// speedup vs baseline: 6.9945x; 1.1149x over previous
#include <cuda_runtime.h>
#include <cstdint>

#define B_  4
#define LQ_ 2048
#define LK_ 2048
#define D_  1024

// ---------------- scratch (static device globals; no runtime alloc) ----------
__device__ float g_wt  [(size_t)3 * D_ * D_];        // W^T rounded, stacked
__device__ float g_bias[3 * D_];                     // biases stacked
__device__ float g_qkv [(size_t)3 * B_ * LQ_ * D_];  // projected q|k|v (tf32-rounded)
__device__ float g_vt  [(size_t)B_ * D_ * LK_];      // V^T per batch (tf32-rounded)
__device__ float g_s   [(size_t)B_ * LQ_ * LK_];     // scores / probs

// ---------------- PTX helpers ------------------------------------------------
__device__ __forceinline__ uint32_t smem_u32(const void* p) {
    uint32_t a;
    asm("{ .reg .u64 t; cvta.to.shared.u64 t, %1; cvt.u32.u64 %0, t; }" : "=r"(a) : "l"(p));
    return a;
}
__device__ __forceinline__ float rna_tf32(float x) {
    uint32_t r; asm("cvt.rna.tf32.f32 %0, %1;" : "=r"(r) : "f"(x));
    return __uint_as_float(r);
}
__device__ __forceinline__ uint32_t rna_tf32_u(uint32_t x) {
    uint32_t r; asm("cvt.rna.tf32.f32 %0, %1;" : "=r"(r) : "f"(__uint_as_float(x)));
    return r;
}
__device__ __forceinline__ void cp16(uint32_t s, const void* g) {
    asm volatile("cp.async.cg.shared.global [%0], [%1], 16;" :: "r"(s), "l"(g));
}
#define CP_COMMIT() asm volatile("cp.async.commit_group;" ::: "memory")
#define CP_WAIT(n)  asm volatile("cp.async.wait_group %0;" :: "n"(n) : "memory")

__device__ __forceinline__ void ldsm4(uint32_t* r, uint32_t addr) {
    asm volatile("ldmatrix.sync.aligned.m8n8.x4.shared.b16 {%0,%1,%2,%3}, [%4];"
        : "=r"(r[0]), "=r"(r[1]), "=r"(r[2]), "=r"(r[3]) : "r"(addr));
}

__device__ __forceinline__ void mma_tf32(float* c, const uint32_t* a, const uint32_t* b) {
    asm volatile(
        "mma.sync.aligned.m16n8k8.row.col.f32.tf32.tf32.f32 "
        "{%0,%1,%2,%3}, {%4,%5,%6,%7}, {%8,%9}, {%0,%1,%2,%3};"
        : "+f"(c[0]), "+f"(c[1]), "+f"(c[2]), "+f"(c[3])
        : "r"(a[0]), "r"(a[1]), "r"(a[2]), "r"(a[3]), "r"(b[0]), "r"(b[1]));
}

// ---------------- tf32 mma.sync NT GEMM --------------------------------------
// C[M,N] = alpha * A[M,K] @ Bt[N,K]^T (+ bias), batched via blockIdx.z.
// Block tile 128x128x32; 128 threads = 4 warps (2 M x 2 N), warp tile 64x64.
// 2 CTAs/SM (smem 110.6KB each). Single __syncthreads per k-iter.
#define BM 128
#define BN 128
#define BK 32
#define RST 36
#define STAGE_FLOATS ((BM + BN) * RST)   // 9216 floats = 36864 B
#define STAGES 3
#define GEMM_SMEM (STAGES * STAGE_FLOATS * 4)

template <bool MULTI_A, bool RND_A, bool BIAS, bool ROUND>
__global__ __launch_bounds__(128, 2)
void gemm_tf32(const float* __restrict__ A0, const float* __restrict__ A1,
               const float* __restrict__ A2, const float* __restrict__ Bt,
               const float* __restrict__ bias, float* __restrict__ C,
               int N, int K, float alpha,
               size_t sA, size_t sB, size_t sC, int sBias)
{
    extern __shared__ float smf[];
    const uint32_t sb32 = smem_u32(smf);

    const int tid  = threadIdx.x;
    const int wid  = tid >> 5;
    const int lane = tid & 31;
    const int grp  = lane >> 2;   // 0..7
    const int q    = lane & 3;    // 0..3
    const int wm   = wid & 1;     // 2 warps along M -> 64 rows
    const int wn   = wid >> 1;    // 2 warps along N -> 64 cols

    const int m0 = blockIdx.y * BM;
    const int n0 = blockIdx.x * BN;
    const int z  = blockIdx.z;

    const float* Ab = MULTI_A ? (z == 0 ? A0 : (z == 1 ? A1 : A2))
                              : A0 + (size_t)z * sA;
    const float* Bb = Bt + (size_t)z * sB;
    const float* biasb = BIAS ? (bias + (size_t)z * sBias) : nullptr;
    float* Cb = C + (size_t)z * sC;

    const int KT = K / BK;

    // per-lane ldmatrix byte offsets (within stage base / B region base)
    const uint32_t aoff =
        ((wm * 64 + (lane & 7) + ((lane >> 3) & 1) * 8) * RST + ((lane >> 4) & 1) * 4) * 4;
    const uint32_t boff =
        ((wn * 64 + (lane & 7) + ((lane >> 4) & 1) * 8) * RST + ((lane >> 3) & 1) * 4) * 4;

    // async load of one stage: A 128x32 + B 128x32, K-major rows (8 x 16B segs)
    auto load_stage = [&](int s, int kt) {
        const uint32_t abase = sb32 + s * STAGE_FLOATS * 4;
        const uint32_t bbase = abase + BM * RST * 4;
        const int k0 = kt * BK;
#pragma unroll
        for (int j = 0; j < 8; j++) {
            const int idx = tid + j * 128;          // 0..1023
            const int row = idx >> 3, seg = idx & 7;
            cp16(abase + (row * RST + seg * 4) * 4,
                 Ab + (size_t)(m0 + row) * K + k0 + seg * 4);
        }
#pragma unroll
        for (int j = 0; j < 8; j++) {
            const int idx = tid + j * 128;
            const int row = idx >> 3, seg = idx & 7;
            cp16(bbase + (row * RST + seg * 4) * 4,
                 Bb + (size_t)(n0 + row) * K + k0 + seg * 4);
        }
        CP_COMMIT();
    };

    float acc[4][8][4];
#pragma unroll
    for (int i = 0; i < 4; i++)
#pragma unroll
        for (int j = 0; j < 8; j++)
#pragma unroll
            for (int r = 0; r < 4; r++) acc[i][j][r] = 0.f;

    load_stage(0, 0);
    load_stage(1, 1);

    for (int kt = 0; kt < KT; kt++) {
        const int s = kt % STAGES;
        if (kt < KT - 1) { CP_WAIT(1); } else { CP_WAIT(0); }
        __syncthreads();

        if (kt + 2 < KT) load_stage((kt + 2) % STAGES, kt + 2);

        const uint32_t sa = sb32 + s * STAGE_FLOATS * 4;
        const uint32_t sbB = sa + BM * RST * 4;

#pragma unroll
        for (int kk = 0; kk < 4; kk++) {
            uint32_t af[4][4], bf[4][4];
#pragma unroll
            for (int mt = 0; mt < 4; mt++)
                ldsm4(af[mt], sa + aoff + mt * (16 * RST * 4) + kk * 32);
            if (RND_A) {
#pragma unroll
                for (int mt = 0; mt < 4; mt++)
#pragma unroll
                    for (int r = 0; r < 4; r++) af[mt][r] = rna_tf32_u(af[mt][r]);
            }
#pragma unroll
            for (int ntp = 0; ntp < 4; ntp++)
                ldsm4(bf[ntp], sbB + boff + ntp * (16 * RST * 4) + kk * 32);
#pragma unroll
            for (int mt = 0; mt < 4; mt++)
#pragma unroll
                for (int nt = 0; nt < 8; nt++)
                    mma_tf32(acc[mt][nt], af[mt], bf[nt >> 1] + (nt & 1) * 2);
        }
    }

    // Epilogue: acc[mt][nt] -> rows r, r+8 ; cols c..c+1
#pragma unroll
    for (int mt = 0; mt < 4; mt++) {
        const int r = m0 + wm * 64 + mt * 16 + grp;
#pragma unroll
        for (int nt = 0; nt < 8; nt++) {
            const int c = n0 + wn * 64 + nt * 8 + q * 2;
            float2 v0, v1;
            v0.x = acc[mt][nt][0] * alpha;
            v0.y = acc[mt][nt][1] * alpha;
            v1.x = acc[mt][nt][2] * alpha;
            v1.y = acc[mt][nt][3] * alpha;
            if (BIAS) {
                const float2 bb = *(const float2*)(biasb + c);
                v0.x += bb.x; v0.y += bb.y;
                v1.x += bb.x; v1.y += bb.y;
            }
            if (ROUND) {
                v0.x = rna_tf32(v0.x); v0.y = rna_tf32(v0.y);
                v1.x = rna_tf32(v1.x); v1.y = rna_tf32(v1.y);
            }
            *(float2*)(Cb + (size_t)r * N + c)       = v0;
            *(float2*)(Cb + (size_t)(r + 8) * N + c) = v1;
        }
    }
}

// ---------------- aux kernels ------------------------------------------------
// in [R,C] row-major -> out [C,R] row-major, tf32-rounded, batched.
__global__ __launch_bounds__(256)
void transpose_round_k(const float* __restrict__ in, float* __restrict__ out,
                       int R, int C, size_t sIn, size_t sOut)
{
    __shared__ float t[32][33];
    const float* ib = in  + (size_t)blockIdx.z * sIn;
    float*       ob = out + (size_t)blockIdx.z * sOut;
    const int c0 = blockIdx.x * 32, r0 = blockIdx.y * 32;
    const int tx = threadIdx.x & 31, ty = threadIdx.x >> 5;  // 32x8
#pragma unroll
    for (int i = 0; i < 32; i += 8)
        t[ty + i][tx] = ib[(size_t)(r0 + ty + i) * C + c0 + tx];
    __syncthreads();
#pragma unroll
    for (int i = 0; i < 32; i += 8)
        ob[(size_t)(c0 + ty + i) * R + r0 + tx] = rna_tf32(t[tx][ty + i]);
}

// Row softmax over LK_ columns; tf32-rounded output.
__global__ __launch_bounds__(256)
void softmax_k(float* __restrict__ S)
{
    __shared__ float red[256];
    float* p = S + (size_t)blockIdx.x * LK_;
    const int tid = threadIdx.x;

    float v[8];
    *(float4*)(v)     = *(const float4*)(p + tid * 8);
    *(float4*)(v + 4) = *(const float4*)(p + tid * 8 + 4);

    float mx = v[0];
#pragma unroll
    for (int i = 1; i < 8; i++) mx = fmaxf(mx, v[i]);
    red[tid] = mx;
    __syncthreads();
    for (int s = 128; s > 0; s >>= 1) {
        if (tid < s) red[tid] = fmaxf(red[tid], red[tid + s]);
        __syncthreads();
    }
    mx = red[0];
    __syncthreads();

    float sum = 0.f;
#pragma unroll
    for (int i = 0; i < 8; i++) { v[i] = __expf(v[i] - mx); sum += v[i]; }
    red[tid] = sum;
    __syncthreads();
    for (int s = 128; s > 0; s >>= 1) {
        if (tid < s) red[tid] += red[tid + s];
        __syncthreads();
    }
    const float inv = 1.f / red[0];
    __syncthreads();

#pragma unroll
    for (int i = 0; i < 8; i++) v[i] = rna_tf32(v[i] * inv);
    *(float4*)(p + tid * 8)     = *(float4*)(v);
    *(float4*)(p + tid * 8 + 4) = *(float4*)(v + 4);
}

// ---------------- host -------------------------------------------------------
extern "C" void kernel_launch(void* const* d_in, const int* in_sizes, int n_in,
                              void* d_out, int out_size)
{
    const float* q_in = (const float*)d_in[0];
    const float* k_in = (const float*)d_in[1];
    const float* v_in = (const float*)d_in[2];
    const float* Wq   = (const float*)d_in[3];
    const float* bq   = (const float*)d_in[4];
    const float* Wk   = (const float*)d_in[5];
    const float* bk   = (const float*)d_in[6];
    const float* Wv   = (const float*)d_in[7];
    const float* bv   = (const float*)d_in[8];
    float* out = (float*)d_out;

    float *pwt, *pbias, *pqkv, *pvt, *ps;
    cudaGetSymbolAddress((void**)&pwt,   g_wt);
    cudaGetSymbolAddress((void**)&pbias, g_bias);
    cudaGetSymbolAddress((void**)&pqkv,  g_qkv);
    cudaGetSymbolAddress((void**)&pvt,   g_vt);
    cudaGetSymbolAddress((void**)&ps,    g_s);

    cudaFuncSetAttribute((const void*)gemm_tf32<true,  true,  true,  true >,
                         cudaFuncAttributeMaxDynamicSharedMemorySize, GEMM_SMEM);
    cudaFuncSetAttribute((const void*)gemm_tf32<false, false, false, false>,
                         cudaFuncAttributeMaxDynamicSharedMemorySize, GEMM_SMEM);

    const size_t T = (size_t)B_ * LQ_ * D_;

    // 1) W^T (rounded), biases stacked
    dim3 tb(256);
    transpose_round_k<<<dim3(D_ / 32, D_ / 32, 1), tb>>>(Wq, pwt + 0 * (size_t)D_ * D_, D_, D_, 0, 0);
    transpose_round_k<<<dim3(D_ / 32, D_ / 32, 1), tb>>>(Wk, pwt + 1 * (size_t)D_ * D_, D_, D_, 0, 0);
    transpose_round_k<<<dim3(D_ / 32, D_ / 32, 1), tb>>>(Wv, pwt + 2 * (size_t)D_ * D_, D_, D_, 0, 0);
    cudaMemcpyAsync(pbias + 0 * D_, bq, D_ * sizeof(float), cudaMemcpyDeviceToDevice);
    cudaMemcpyAsync(pbias + 1 * D_, bk, D_ * sizeof(float), cudaMemcpyDeviceToDevice);
    cudaMemcpyAsync(pbias + 2 * D_, bv, D_ * sizeof(float), cudaMemcpyDeviceToDevice);

    // 2) projections: batched over z (q|k|v), A rounded in-register, out rounded
    gemm_tf32<true, true, true, true><<<dim3(D_ / BN, (B_ * LQ_) / BM, 3), 128, GEMM_SMEM>>>(
        q_in, k_in, v_in, pwt, pbias, pqkv, D_, D_, 1.f,
        0, (size_t)D_ * D_, T, D_);

    // 3) V^T per batch (rounded)
    transpose_round_k<<<dim3(D_ / 32, LK_ / 32, B_), tb>>>(
        pqkv + 2 * T, pvt, LK_, D_, (size_t)LK_ * D_, (size_t)D_ * LK_);

    // 4) scores S = (Q K^T) / 32
    gemm_tf32<false, false, false, false><<<dim3(LK_ / BN, LQ_ / BM, B_), 128, GEMM_SMEM>>>(
        pqkv + 0 * T, nullptr, nullptr, pqkv + 1 * T, nullptr, ps, LK_, D_, 1.f / 32.f,
        (size_t)LQ_ * D_, (size_t)LK_ * D_, (size_t)LQ_ * LK_, 0);

    // 5) softmax rows (tf32-rounded probs)
    softmax_k<<<B_ * LQ_, 256>>>(ps);

    // 6) O = P @ V  (V^T is [D, LK] K-major)
    gemm_tf32<false, false, false, false><<<dim3(D_ / BN, LQ_ / BM, B_), 128, GEMM_SMEM>>>(
        ps, nullptr, nullptr, pvt, nullptr, out, D_, LK_, 1.f,
        (size_t)LQ_ * LK_, (size_t)D_ * LK_, (size_t)LQ_ * D_, 0);
}